// round 14
// baseline (speedup 1.0000x reference)
#include <cuda_runtime.h>
#include <cuda_bf16.h>
#include <cstdint>

// ---------------------------------------------------------------------------
// Problem constants
// ---------------------------------------------------------------------------
#define HID 512
#define POOL 4096
#define NUM_OBJ 151
#define NUM_REL 51
#define KLR 100
#define N_OBJ 4096
#define N_REL 16384
#define KCAT (2*KLR + POOL)   // 4296
#define KCATP 4352            // padded to 64
#define KRC 5120              // merged output GEMM K: 4096 (visual) + 1024 (P)

// ---------------------------------------------------------------------------
// Scratch (device globals; no allocation allowed)
// ---------------------------------------------------------------------------
__device__ float g_edge_rep[(size_t)N_OBJ * 1024];
__device__ float g_tmp[(size_t)N_REL * 400];
__device__ float g_y[(size_t)N_REL * POOL];
__device__ float g_colsum_part[64 * 200];
__device__ float g_usvs[200];
__device__ float g_vtz_part[64 * 10000];
__device__ float g_vtz[10000];
__device__ float g_dscale[1];
__device__ float g_bias_rc[64];

// bf16 hi/lo activation buffers
__device__ __nv_bfloat16 gU_hi[(size_t)N_REL * POOL];
__device__ __nv_bfloat16 gU_lo[(size_t)N_REL * POOL];
__device__ __nv_bfloat16 gXc_hi[(size_t)N_REL * KCATP];
__device__ __nv_bfloat16 gXc_lo[(size_t)N_REL * KCATP];
__device__ __nv_bfloat16 gP_hi[(size_t)N_REL * 1024];
__device__ __nv_bfloat16 gP_lo[(size_t)N_REL * 1024];
__device__ __nv_bfloat16 gE_hi[(size_t)N_OBJ * 512];
__device__ __nv_bfloat16 gE_lo[(size_t)N_OBJ * 512];
// bf16 hi/lo weights (transposed to [N, Kpad])
__device__ __nv_bfloat16 gWpe_hi[1024 * 512],  gWpe_lo[1024 * 512];
__device__ __nv_bfloat16 gWpc_hi[4096 * 1024], gWpc_lo[4096 * 1024];
__device__ __nv_bfloat16 gWa1_hi[512 * 4096],  gWa1_lo[512 * 4096];
__device__ __nv_bfloat16 gWd1_hi[(size_t)4096 * KCATP], gWd1_lo[(size_t)4096 * KCATP];
__device__ __nv_bfloat16 gWa2_hi[512 * 4096],  gWa2_lo[512 * 4096];
__device__ __nv_bfloat16 gWd2_hi[(size_t)4096 * KCATP], gWd2_lo[(size_t)4096 * KCATP];
__device__ __nv_bfloat16 gWrc_hi[(size_t)128 * KRC], gWrc_lo[(size_t)128 * KRC];

// ---------------------------------------------------------------------------
// PTX helpers (plain sm_80+ PTX — harness ptxas targets bare sm_103)
// ---------------------------------------------------------------------------
__device__ __forceinline__ uint32_t s2u(const void* p) {
    uint32_t a;
    asm("{ .reg .u64 t; cvta.to.shared.u64 t, %1; cvt.u32.u64 %0, t; }" : "=r"(a) : "l"(p));
    return a;
}
#define CP_ASYNC16(dst, src) \
    asm volatile("cp.async.cg.shared.global [%0], [%1], 16;" :: "r"(dst), "l"(src))
#define CP_COMMIT() asm volatile("cp.async.commit_group;" ::: "memory")
#define CP_WAIT1()  asm volatile("cp.async.wait_group 1;" ::: "memory")

__device__ __forceinline__ void ldsm4(uint32_t* r, uint32_t addr) {
    asm volatile("ldmatrix.sync.aligned.m8n8.x4.shared.b16 {%0,%1,%2,%3}, [%4];"
        : "=r"(r[0]), "=r"(r[1]), "=r"(r[2]), "=r"(r[3]) : "r"(addr));
}
__device__ __forceinline__ void mma_bf16(float* d, const uint32_t* a, const uint32_t* b) {
    asm volatile(
        "mma.sync.aligned.m16n8k16.row.col.f32.bf16.bf16.f32 "
        "{%0,%1,%2,%3}, {%4,%5,%6,%7}, {%8,%9}, {%0,%1,%2,%3};"
        : "+f"(d[0]), "+f"(d[1]), "+f"(d[2]), "+f"(d[3])
        : "r"(a[0]), "r"(a[1]), "r"(a[2]), "r"(a[3]), "r"(b[0]), "r"(b[1]));
}

__device__ __forceinline__ void split_hl(float v, __nv_bfloat16& h, __nv_bfloat16& l) {
    h = __float2bfloat16(v);
    l = __float2bfloat16(v - __bfloat162float(h));
}

// XOR-swizzled smem layout: row r (0..127), 16B-chunk c (0..3); 64B rows.
__device__ __forceinline__ uint32_t swz(uint32_t r, uint32_t c) {
    return r * 64u + ((c ^ ((r >> 1) & 3u)) << 4);
}

// ---------------------------------------------------------------------------
// HMMA GEMM: C = epi(A @ B^T), hi/lo bf16 3-pass fp32 emulation.
// 128x128 tile, BK=32, 128 threads (4 warps, each 64x64).
// 3-stage cp.async pipeline, ONE __syncthreads per K-chunk, 2 CTAs/SM.
// B-fragment double-buffering hides LDSM latency behind the MMA burst.
// Supports dual-source A (Ksplit) for the merged output GEMM.
// ---------------------------------------------------------------------------
#define EPI_BIAS      0
#define EPI_RELU      1
#define EPI_MULRELU   2   // OUT=1: also splits 'extra' into Euhi/Eulo
#define EPI_BIASFREQ  5   // C = v + bias[col] + freq[(p0*NUM_OBJ+p1)*NUM_REL+col]
// OUT: 0 = fp32 C;  1 = bf16 hi/lo pair (Dhi/Dlo)

#define MAT_BYTES 8192u                    // 128 rows x 64B
#define STAGE_BYTES (4u * MAT_BYTES)       // 32768
#define HM_DSMEM (3 * 32768)               // 98304 -> 2 CTAs/SM

__device__ __forceinline__ void hm_load_stage(
    uint32_t st, int t,
    const __nv_bfloat16* __restrict__ Ahi, const __nv_bfloat16* __restrict__ Alo,
    int lda, int bm0,
    const __nv_bfloat16* __restrict__ Bhi, const __nv_bfloat16* __restrict__ Blo,
    int ldb, int bn0, int k0,
    const __nv_bfloat16* __restrict__ A2hi, const __nv_bfloat16* __restrict__ A2lo,
    int lda2, int Ksplit)
{
    const __nv_bfloat16* sAh = Ahi;
    const __nv_bfloat16* sAl = Alo;
    int sLda = lda, scol = k0;
    if (k0 >= Ksplit) { sAh = A2hi; sAl = A2lo; sLda = lda2; scol = k0 - Ksplit; }
#pragma unroll
    for (int i = 0; i < 4; i++) {
        int q = t + (i << 7);                 // 512 quads
        uint32_t r = (uint32_t)(q >> 2), c = (uint32_t)(q & 3);
        uint32_t dst = st + swz(r, c);
        int acol = scol + (int)c * 8;
        int bcol = k0 + (int)c * 8;
        CP_ASYNC16(dst,                   sAh + (size_t)(bm0 + (int)r) * sLda + acol);
        CP_ASYNC16(dst + MAT_BYTES,       sAl + (size_t)(bm0 + (int)r) * sLda + acol);
        CP_ASYNC16(dst + 2u * MAT_BYTES,  Bhi + (size_t)(bn0 + (int)r) * ldb + bcol);
        CP_ASYNC16(dst + 3u * MAT_BYTES,  Blo + (size_t)(bn0 + (int)r) * ldb + bcol);
    }
}

template<int EPI>
__device__ __forceinline__ float hm_epi(float v, int row, int col,
    const float* __restrict__ bias, const float* __restrict__ extra, int lde,
    const float* __restrict__ C, int ldc,
    const float* __restrict__ freq_row)
{
    if (EPI == EPI_BIAS)         return v + bias[col];
    else if (EPI == EPI_RELU)    return fmaxf(v + bias[col], 0.f);
    else if (EPI == EPI_MULRELU) return fmaxf(extra[(size_t)row * lde + col] * (v + bias[col]), 0.f);
    else                         return v + bias[col] + freq_row[col];
}

template<int EPI, int OUT>
__global__ void __launch_bounds__(128, 2)
hm_gemm(const __nv_bfloat16* __restrict__ Ahi, const __nv_bfloat16* __restrict__ Alo, int lda,
        const __nv_bfloat16* __restrict__ Bhi, const __nv_bfloat16* __restrict__ Blo, int ldb,
        const float* __restrict__ bias, const float* __restrict__ extra, int lde,
        float* __restrict__ C, int ldc,
        __nv_bfloat16* __restrict__ Dhi, __nv_bfloat16* __restrict__ Dlo, int ldd,
        int ncols, int K,
        const int* __restrict__ pairs, const int* __restrict__ obj_preds,
        const float* __restrict__ freq,
        const __nv_bfloat16* __restrict__ A2hi, const __nv_bfloat16* __restrict__ A2lo,
        int lda2, int Ksplit,
        __nv_bfloat16* __restrict__ Euhi, __nv_bfloat16* __restrict__ Eulo)
{
    extern __shared__ char dsm[];
    const uint32_t sb = s2u(dsm);
    const int t = threadIdx.x, w = t >> 5, l = t & 31;
    const int bm0 = blockIdx.y * 128, bn0 = blockIdx.x * 128;
    const int wm = (w >> 1) * 64, wn = (w & 1) * 64;   // 2x2 warp grid, 64x64 each

    const uint32_t a_row = (uint32_t)(((l >> 3) & 1) * 8 + (l & 7));
    const uint32_t a_ch  = (uint32_t)(l >> 4);
    const uint32_t b_row = (uint32_t)((l >> 4) * 8 + (l & 7));
    const uint32_t b_ch  = (uint32_t)((l >> 3) & 1);

    float acc[4][8][4];
#pragma unroll
    for (int i = 0; i < 4; i++)
#pragma unroll
        for (int j = 0; j < 8; j++)
#pragma unroll
            for (int q = 0; q < 4; q++) acc[i][j][q] = 0.f;

    const int nk = K >> 5;
    hm_load_stage(sb, t, Ahi, Alo, lda, bm0, Bhi, Blo, ldb, bn0, 0,
                  A2hi, A2lo, lda2, Ksplit);
    CP_COMMIT();
    hm_load_stage(sb + STAGE_BYTES, t, Ahi, Alo, lda, bm0, Bhi, Blo, ldb, bn0, 32,
                  A2hi, A2lo, lda2, Ksplit);
    CP_COMMIT();

    for (int j = 0; j < nk; j++) {
        CP_WAIT1();
        __syncthreads();                       // single barrier per chunk
        if (j + 2 < nk)
            hm_load_stage(sb + (uint32_t)((j + 2) % 3) * STAGE_BYTES, t,
                          Ahi, Alo, lda, bm0, Bhi, Blo, ldb, bn0, (j + 2) * 32,
                          A2hi, A2lo, lda2, Ksplit);
        CP_COMMIT();

        uint32_t st = sb + (uint32_t)(j % 3) * STAGE_BYTES;
#pragma unroll
        for (int ks = 0; ks < 2; ks++) {
            const uint32_t kc = (uint32_t)ks * 2u;
            const uint32_t boff = b_row * 64u;   // partial; full addr via swz below
            uint32_t Ah[4][4], Al[4][4];
#pragma unroll
            for (int mi = 0; mi < 4; mi++)
                ldsm4(Ah[mi], st + swz((uint32_t)(wm + mi * 16) + a_row, kc + a_ch));
#pragma unroll
            for (int mi = 0; mi < 4; mi++)
                ldsm4(Al[mi], st + MAT_BYTES + swz((uint32_t)(wm + mi * 16) + a_row, kc + a_ch));

            // B fragment double buffer: prefetch nj+1 while computing nj
            uint32_t Bh[2][4], Bl[2][4];
            ldsm4(Bh[0], st + 2u * MAT_BYTES + swz((uint32_t)(wn + 0) + b_row, kc + b_ch));
            ldsm4(Bl[0], st + 3u * MAT_BYTES + swz((uint32_t)(wn + 0) + b_row, kc + b_ch));
#pragma unroll
            for (int nj = 0; nj < 4; nj++) {
                const int cur = nj & 1, nxt = cur ^ 1;
                if (nj < 3) {
                    ldsm4(Bh[nxt], st + 2u * MAT_BYTES +
                          swz((uint32_t)(wn + (nj + 1) * 16) + b_row, kc + b_ch));
                    ldsm4(Bl[nxt], st + 3u * MAT_BYTES +
                          swz((uint32_t)(wn + (nj + 1) * 16) + b_row, kc + b_ch));
                }
#pragma unroll
                for (int mi = 0; mi < 4; mi++) {
                    mma_bf16(acc[mi][nj * 2 + 0], Ah[mi], &Bh[cur][0]);
                    mma_bf16(acc[mi][nj * 2 + 1], Ah[mi], &Bh[cur][2]);
                }
#pragma unroll
                for (int mi = 0; mi < 4; mi++) {
                    mma_bf16(acc[mi][nj * 2 + 0], Ah[mi], &Bl[cur][0]);
                    mma_bf16(acc[mi][nj * 2 + 1], Ah[mi], &Bl[cur][2]);
                }
#pragma unroll
                for (int mi = 0; mi < 4; mi++) {
                    mma_bf16(acc[mi][nj * 2 + 0], Al[mi], &Bh[cur][0]);
                    mma_bf16(acc[mi][nj * 2 + 1], Al[mi], &Bh[cur][2]);
                }
            }
            (void)boff;
        }
    }

    // epilogue
    const int rl = l >> 2, cl = (l & 3) * 2;
    const bool ldc_even = ((ldc & 1) == 0);
#pragma unroll
    for (int mi = 0; mi < 4; mi++) {
#pragma unroll
        for (int ni = 0; ni < 8; ni++) {
            int row0 = bm0 + wm + mi * 16 + rl;
            int col0 = bn0 + wn + ni * 8 + cl;
#pragma unroll
            for (int h = 0; h < 2; h++) {
                int row = row0 + h * 8;
                float v0 = acc[mi][ni][h * 2 + 0];
                float v1 = acc[mi][ni][h * 2 + 1];
                const float* freq_row = nullptr;
                if (EPI == EPI_BIASFREQ) {
                    int p0 = obj_preds[pairs[2 * row]];
                    int p1 = obj_preds[pairs[2 * row + 1]];
                    freq_row = freq + ((size_t)p0 * NUM_OBJ + p1) * NUM_REL;
                }
                if (OUT == 1) {
                    if (col0 + 1 < ncols) {
                        float o0, o1;
                        if (EPI == EPI_MULRELU) {
                            float2 e = *(const float2*)(extra + (size_t)row * lde + col0);
                            o0 = fmaxf(e.x * (v0 + bias[col0]), 0.f);
                            o1 = fmaxf(e.y * (v1 + bias[col0 + 1]), 0.f);
                            __nv_bfloat16 uh0, ul0, uh1, ul1;
                            split_hl(e.x, uh0, ul0); split_hl(e.y, uh1, ul1);
                            __nv_bfloat162 pu; pu.x = uh0; pu.y = uh1;
                            __nv_bfloat162 qu; qu.x = ul0; qu.y = ul1;
                            *(__nv_bfloat162*)(Euhi + (size_t)row * lde + col0) = pu;
                            *(__nv_bfloat162*)(Eulo + (size_t)row * lde + col0) = qu;
                        } else {
                            o0 = hm_epi<EPI>(v0, row, col0,     bias, extra, lde, C, ldc, freq_row);
                            o1 = hm_epi<EPI>(v1, row, col0 + 1, bias, extra, lde, C, ldc, freq_row);
                        }
                        __nv_bfloat16 h0, l0, h1, l1;
                        split_hl(o0, h0, l0); split_hl(o1, h1, l1);
                        __nv_bfloat162 ph; ph.x = h0; ph.y = h1;
                        __nv_bfloat162 pl; pl.x = l0; pl.y = l1;
                        *(__nv_bfloat162*)(Dhi + (size_t)row * ldd + col0) = ph;
                        *(__nv_bfloat162*)(Dlo + (size_t)row * ldd + col0) = pl;
                    }
                } else if (ldc_even && col0 + 1 < ncols) {
                    float2 o;
                    o.x = hm_epi<EPI>(v0, row, col0,     bias, extra, lde, C, ldc, freq_row);
                    o.y = hm_epi<EPI>(v1, row, col0 + 1, bias, extra, lde, C, ldc, freq_row);
                    *(float2*)(C + (size_t)row * ldc + col0) = o;
                } else {
                    if (col0 < ncols)
                        C[(size_t)row * ldc + col0] =
                            hm_epi<EPI>(v0, row, col0, bias, extra, lde, C, ldc, freq_row);
                    if (col0 + 1 < ncols)
                        C[(size_t)row * ldc + col0 + 1] =
                            hm_epi<EPI>(v1, row, col0 + 1, bias, extra, lde, C, ldc, freq_row);
                }
            }
        }
    }
}

// ---------------------------------------------------------------------------
// Conversions
// ---------------------------------------------------------------------------
__global__ void conv_hl(const float* __restrict__ in, int C,
                        __nv_bfloat16* __restrict__ hi, __nv_bfloat16* __restrict__ lo,
                        int Cpad, long total4)
{
    long i = (long)blockIdx.x * blockDim.x + threadIdx.x;
    if (i >= total4) return;
    long e = i * 4;
    long r = e / Cpad;
    int c = (int)(e - r * Cpad);
    float4 v;
    if (c < C) v = *(const float4*)(in + r * C + c);
    else { v.x = v.y = v.z = v.w = 0.f; }
    __nv_bfloat16 h[4], l[4];
    split_hl(v.x, h[0], l[0]); split_hl(v.y, h[1], l[1]);
    split_hl(v.z, h[2], l[2]); split_hl(v.w, h[3], l[3]);
    *(uint2*)(hi + e) = *(uint2*)h;
    *(uint2*)(lo + e) = *(uint2*)l;
}

// [K,N] fp32 -> transposed [N,Kpad] hi/lo bf16; 64x64 tiles, vectorized stores.
__global__ void __launch_bounds__(256)
conv_T_hl(const float* __restrict__ in, int K, int N,
          __nv_bfloat16* __restrict__ hi, __nv_bfloat16* __restrict__ lo,
          int Kpad)
{
    __shared__ float tile[64][65];
    const int k0 = blockIdx.x * 64, n0 = blockIdx.y * 64;
    const int t = threadIdx.x;
    const int tn = t & 63, tk = t >> 6;
#pragma unroll
    for (int q = 0; q < 16; q++) {
        int k = k0 + tk + q * 4, n = n0 + tn;
        tile[tk + q * 4][tn] = (k < K && n < N) ? in[(size_t)k * N + n] : 0.f;
    }
    __syncthreads();
    const int kg = t & 15;
    const int nr = t >> 4;
#pragma unroll
    for (int q = 0; q < 4; q++) {
        int nrow = n0 + nr + q * 16;
        int kc = k0 + kg * 4;
        if (nrow < N && kc < Kpad) {
            __nv_bfloat16 h[4], l[4];
#pragma unroll
            for (int e = 0; e < 4; e++)
                split_hl(tile[kg * 4 + e][nr + q * 16], h[e], l[e]);
            *(uint2*)(hi + (size_t)nrow * Kpad + kc) = *(uint2*)h;
            *(uint2*)(lo + (size_t)nrow * Kpad + kc) = *(uint2*)l;
        }
    }
}

// zero the 56 pad columns of the Xc slab
__global__ void pad_xc(__nv_bfloat16* __restrict__ hi, __nv_bfloat16* __restrict__ lo)
{
    int row = blockIdx.x, c = threadIdx.x;
    if (c < KCATP - KCAT) {
        size_t idx = (size_t)row * KCATP + KCAT + c;
        hi[idx] = __float2bfloat16(0.f);
        lo[idx] = __float2bfloat16(0.f);
    }
}

__global__ void combine_bias(const float* __restrict__ b_rel,
                             const float* __restrict__ b_ctx,
                             float* __restrict__ out)
{
    int c = threadIdx.x;
    if (c < NUM_REL) out[c] = b_rel[c] + b_ctx[c];
    else if (c < 64) out[c] = 0.f;
}

// fused gather + hi/lo split
__global__ void gather_hl(const float* __restrict__ edge_rep,
                          const int* __restrict__ pairs,
                          __nv_bfloat16* __restrict__ Phi,
                          __nv_bfloat16* __restrict__ Plo)
{
    int i = blockIdx.x;
    int s = pairs[2 * i], o = pairs[2 * i + 1];
    for (int c4 = threadIdx.x; c4 < 256; c4 += blockDim.x) {
        const float4* src = (c4 < 128)
            ? (const float4*)(edge_rep + (size_t)s * 1024) + c4
            : (const float4*)(edge_rep + (size_t)o * 1024 + 512) + (c4 - 128);
        float4 v = *src;
        __nv_bfloat16 h[4], l[4];
        split_hl(v.x, h[0], l[0]); split_hl(v.y, h[1], l[1]);
        split_hl(v.z, h[2], l[2]); split_hl(v.w, h[3], l[3]);
        size_t e = (size_t)i * 1024 + c4 * 4;
        *(uint2*)(Phi + e) = *(uint2*)h;
        *(uint2*)(Plo + e) = *(uint2*)l;
    }
}

// ---------------------------------------------------------------------------
// fp32 FFMA2 GEMM for tiny u@vtz -> Xc cols [0,100); fused t-copy -> [100,200)
// ---------------------------------------------------------------------------
typedef unsigned long long u64;
__device__ __forceinline__ u64 pack2(float lo, float hi) {
    u64 r; asm("mov.b64 %0, {%1,%2};" : "=l"(r) : "f"(lo), "f"(hi)); return r;
}
__device__ __forceinline__ float2 unpack2(u64 v) {
    float2 r; asm("mov.b64 {%0,%1}, %2;" : "=f"(r.x), "=f"(r.y) : "l"(v)); return r;
}
__device__ __forceinline__ void fma2(u64 &c, u64 a, u64 b) {
    asm("fma.rn.f32x2 %0, %1, %2, %3;" : "=l"(c) : "l"(a), "l"(b), "l"(c));
}

__global__ void __launch_bounds__(256, 2)
gemm_scalerelu_hl(const float* __restrict__ A, int lda,
                  const float* __restrict__ B, int ldb,
                  const float* __restrict__ dscale_ptr,
                  __nv_bfloat16* __restrict__ Dhi, __nv_bfloat16* __restrict__ Dlo,
                  int ldd, int M, int N, int K)
{
    __shared__ __align__(16) float As[8][132];
    __shared__ __align__(16) float Bs[8][128];
    const int t = threadIdx.x;
    const int tx = t & 15, ty = t >> 4;
    const int bn0 = blockIdx.x * 128, bm0 = blockIdx.y * 128;
    const int a_m = t >> 1, a_k = (t & 1) * 4;
    const int b_k = t >> 5, b_n = (t & 31) * 4;
    u64 acc[8][4];
#pragma unroll
    for (int i = 0; i < 8; i++)
#pragma unroll
        for (int j = 0; j < 4; j++) acc[i][j] = 0ull;
    for (int k0 = 0; k0 < K; k0 += 8) {
#pragma unroll
        for (int q = 0; q < 4; q++) {
            int kk = k0 + a_k + q, rr = bm0 + a_m;
            As[a_k + q][a_m] = (rr < M && kk < K) ? A[(size_t)rr * lda + kk] : 0.f;
        }
#pragma unroll
        for (int q = 0; q < 4; q++) {
            int nn = bn0 + b_n + q, kk = k0 + b_k;
            Bs[b_k][b_n + q] = (kk < K && nn < N) ? B[(size_t)kk * ldb + nn] : 0.f;
        }
        __syncthreads();
#pragma unroll
        for (int kk = 0; kk < 8; kk++) {
            float4 a0 = *(const float4*)&As[kk][ty * 8];
            float4 a1 = *(const float4*)&As[kk][ty * 8 + 4];
            u64 b2[4];
            *(ulonglong2*)&b2[0] = *(const ulonglong2*)&Bs[kk][tx * 8];
            *(ulonglong2*)&b2[2] = *(const ulonglong2*)&Bs[kk][tx * 8 + 4];
            float af[8] = {a0.x, a0.y, a0.z, a0.w, a1.x, a1.y, a1.z, a1.w};
#pragma unroll
            for (int i = 0; i < 8; i++) {
                u64 a2 = pack2(af[i], af[i]);
                fma2(acc[i][0], a2, b2[0]); fma2(acc[i][1], a2, b2[1]);
                fma2(acc[i][2], a2, b2[2]); fma2(acc[i][3], a2, b2[3]);
            }
        }
        __syncthreads();
    }
    float d = *dscale_ptr;
#pragma unroll
    for (int i = 0; i < 8; i++) {
        int row = bm0 + ty * 8 + i;
        if (row >= M) continue;
#pragma unroll
        for (int jj = 0; jj < 4; jj++) {
            float2 v = unpack2(acc[i][jj]);
            int c0 = bn0 + tx * 8 + jj * 2;
            if (c0 + 1 < N) {
                __nv_bfloat16 h0, l0, h1, l1;
                split_hl(fmaxf(v.x * d, 0.f), h0, l0);
                split_hl(fmaxf(v.y * d, 0.f), h1, l1);
                __nv_bfloat162 ph; ph.x = h0; ph.y = h1;
                __nv_bfloat162 pl; pl.x = l0; pl.y = l1;
                *(__nv_bfloat162*)(Dhi + (size_t)row * ldd + c0) = ph;
                *(__nv_bfloat162*)(Dlo + (size_t)row * ldd + c0) = pl;
            }
        }
    }
    // fused copy of t-part (tmp cols [300,400), already relu'd) -> Xc cols [100,200)
    for (int idx = t; idx < 128 * 100; idx += 256) {
        int r = idx / 100, c = idx % 100;
        int row = bm0 + r;
        if (row < M) {
            float v = A[(size_t)row * lda + 300 + c];
            __nv_bfloat16 h, l;
            split_hl(v, h, l);
            size_t o = (size_t)row * ldd + 100 + c;
            Dhi[o] = h; Dlo[o] = l;
        }
    }
}

// ---------------------------------------------------------------------------
// Fused LRGA reductions: colsum partials + vtz partials in ONE pass over tmp.
// ---------------------------------------------------------------------------
__global__ void __launch_bounds__(320)
lrga_part(const float* __restrict__ tmp, int ld,
          float* __restrict__ cs_part, float* __restrict__ vz_part, int M)
{
    __shared__ float sval[304];
    int t = threadIdx.x;
    int a_base = (t % 20) * 5;
    int b_base = (t / 20) * 10;
    float csum = 0.f;
    float acc[50];
#pragma unroll
    for (int q = 0; q < 50; q++) acc[q] = 0.f;

    for (int r = blockIdx.x; r < M; r += gridDim.x) {
        if (t < 300) sval[t] = tmp[(size_t)r * ld + t];
        __syncthreads();
        if (t < 200) {
            csum += sval[t];
            float zr[10];
#pragma unroll
            for (int j = 0; j < 10; j++) zr[j] = sval[200 + b_base + j];
#pragma unroll
            for (int ia = 0; ia < 5; ia++) {
                float va = sval[100 + a_base + ia];
#pragma unroll
                for (int j = 0; j < 10; j++) acc[ia * 10 + j] += va * zr[j];
            }
        }
        __syncthreads();
    }
    if (t < 200) {
        cs_part[blockIdx.x * 200 + t] = csum;
#pragma unroll
        for (int ia = 0; ia < 5; ia++)
#pragma unroll
            for (int j = 0; j < 10; j++)
                vz_part[(size_t)blockIdx.x * 10000 + (a_base + ia) * 100 + b_base + j] = acc[ia * 10 + j];
    }
}

__global__ void lrga_finish(const float* __restrict__ cs_part,
                            float* __restrict__ usvs, float* __restrict__ dout)
{
    __shared__ float red[128];
    int t = threadIdx.x;
    float s = 0.f;
    if (t < 200) {
        for (int b = 0; b < 64; b++) s += cs_part[b * 200 + t];
        usvs[t] = s;
    }
    __syncthreads();
    float v = (t < 100) ? usvs[t] * usvs[100 + t] : 0.f;
    if (t < 128) red[t] = v;
    __syncthreads();
    for (int st = 64; st > 0; st >>= 1) {
        if (t < st) red[t] += red[t + st];
        __syncthreads();
    }
    if (t == 0) dout[0] = 1.f / (red[0] / (float)N_REL + 1e-6f);
}

__global__ void vtz_reduce(const float* __restrict__ part, float* __restrict__ out)
{
    int idx = blockIdx.x * 256 + threadIdx.x;
    if (idx >= 10000) return;
    float s = 0.f;
    for (int b = 0; b < 64; b++) s += part[(size_t)b * 10000 + idx];
    out[idx] = s;
}

__global__ void groupnorm_hl(const float* __restrict__ y,
                             const float* __restrict__ gamma,
                             const float* __restrict__ beta,
                             __nv_bfloat16* __restrict__ Uhi,
                             __nv_bfloat16* __restrict__ Ulo,
                             __nv_bfloat16* __restrict__ Xchi,
                             __nv_bfloat16* __restrict__ Xclo)
{
    int row = blockIdx.x;
    int w = threadIdx.x >> 5, l = threadIdx.x & 31;
    const float* p = y + (size_t)row * POOL + w * 512;
    float vals[16];
    float s = 0.f, ss = 0.f;
#pragma unroll
    for (int i = 0; i < 16; i++) {
        float v = p[l + i * 32];
        vals[i] = v; s += v; ss += v * v;
    }
#pragma unroll
    for (int off = 16; off > 0; off >>= 1) {
        s  += __shfl_xor_sync(0xffffffffu, s,  off);
        ss += __shfl_xor_sync(0xffffffffu, ss, off);
    }
    float mean = s * (1.f / 512.f);
    float var  = fmaxf(ss * (1.f / 512.f) - mean * mean, 0.f);
    float rstd = rsqrtf(var + 1e-5f);
#pragma unroll
    for (int i = 0; i < 16; i++) {
        int c = w * 512 + l + i * 32;
        float xn = (vals[i] - mean) * rstd * gamma[c] + beta[c];
        __nv_bfloat16 h, lo_;
        split_hl(xn, h, lo_);
        size_t ui = (size_t)row * POOL + c;
        Uhi[ui] = h; Ulo[ui] = lo_;
        float r = fmaxf(xn, 0.f);
        split_hl(r, h, lo_);
        size_t xi = (size_t)row * KCATP + 200 + c;
        Xchi[xi] = h; Xclo[xi] = lo_;
    }
}

// ---------------------------------------------------------------------------
// Launch
// ---------------------------------------------------------------------------
static inline void conv_rows(const float* in, int C, __nv_bfloat16* hi, __nv_bfloat16* lo,
                             int Cpad, long R)
{
    long total4 = R * Cpad / 4;
    conv_hl<<<(unsigned)((total4 + 255) / 256), 256>>>(in, C, hi, lo, Cpad, total4);
}

#define HM_NOEXTRA nullptr, nullptr, nullptr, nullptr, nullptr, 0, (1 << 30), nullptr, nullptr

extern "C" void kernel_launch(void* const* d_in, const int* in_sizes, int n_in,
                              void* d_out, int out_size)
{
    const float* edge_ctx   = (const float*)d_in[0];
    const float* union_feat = (const float*)d_in[1];
    const int*   rel_pairs  = (const int*)  d_in[2];
    const int*   obj_preds  = (const int*)  d_in[3];
    const float* w_post_emb = (const float*)d_in[4];
    const float* b_post_emb = (const float*)d_in[5];
    const float* w_post_cat = (const float*)d_in[6];
    const float* b_post_cat = (const float*)d_in[7];
    const float* w_attn1    = (const float*)d_in[8];
    const float* b_attn1    = (const float*)d_in[9];
    const float* w_dr1      = (const float*)d_in[10];
    const float* b_dr1      = (const float*)d_in[11];
    const float* gn_gamma   = (const float*)d_in[12];
    const float* gn_beta    = (const float*)d_in[13];
    const float* w_attn2    = (const float*)d_in[14];
    const float* b_attn2    = (const float*)d_in[15];
    const float* w_dr2      = (const float*)d_in[16];
    const float* b_dr2      = (const float*)d_in[17];
    const float* w_rel      = (const float*)d_in[18];
    const float* b_rel      = (const float*)d_in[19];
    const float* w_ctx      = (const float*)d_in[20];
    const float* b_ctx      = (const float*)d_in[21];
    const float* freq_table = (const float*)d_in[22];
    float* out = (float*)d_out;

    cudaFuncSetAttribute(hm_gemm<EPI_BIAS,0>,     cudaFuncAttributeMaxDynamicSharedMemorySize, HM_DSMEM);
    cudaFuncSetAttribute(hm_gemm<EPI_BIAS,1>,     cudaFuncAttributeMaxDynamicSharedMemorySize, HM_DSMEM);
    cudaFuncSetAttribute(hm_gemm<EPI_RELU,0>,     cudaFuncAttributeMaxDynamicSharedMemorySize, HM_DSMEM);
    cudaFuncSetAttribute(hm_gemm<EPI_MULRELU,1>,  cudaFuncAttributeMaxDynamicSharedMemorySize, HM_DSMEM);
    cudaFuncSetAttribute(hm_gemm<EPI_BIASFREQ,0>, cudaFuncAttributeMaxDynamicSharedMemorySize, HM_DSMEM);

    void* p;
    cudaGetSymbolAddress(&p, g_edge_rep);    float* edge_rep = (float*)p;
    cudaGetSymbolAddress(&p, g_tmp);         float* tmp      = (float*)p;
    cudaGetSymbolAddress(&p, g_y);           float* ybuf     = (float*)p;
    cudaGetSymbolAddress(&p, g_colsum_part); float* cs_part  = (float*)p;
    cudaGetSymbolAddress(&p, g_usvs);        float* usvs     = (float*)p;
    cudaGetSymbolAddress(&p, g_vtz_part);    float* vz_part  = (float*)p;
    cudaGetSymbolAddress(&p, g_vtz);         float* vtz      = (float*)p;
    cudaGetSymbolAddress(&p, g_dscale);      float* dscale   = (float*)p;
    cudaGetSymbolAddress(&p, g_bias_rc);     float* bias_rc  = (float*)p;

    __nv_bfloat16 *Uhi, *Ulo, *Xchi, *Xclo, *Phi, *Plo, *Ehi, *Elo;
    __nv_bfloat16 *WpeH, *WpeL, *WpcH, *WpcL, *Wa1H, *Wa1L, *Wd1H, *Wd1L;
    __nv_bfloat16 *Wa2H, *Wa2L, *Wd2H, *Wd2L, *WrcH, *WrcL;
    cudaGetSymbolAddress(&p, gU_hi);  Uhi  = (__nv_bfloat16*)p;
    cudaGetSymbolAddress(&p, gU_lo);  Ulo  = (__nv_bfloat16*)p;
    cudaGetSymbolAddress(&p, gXc_hi); Xchi = (__nv_bfloat16*)p;
    cudaGetSymbolAddress(&p, gXc_lo); Xclo = (__nv_bfloat16*)p;
    cudaGetSymbolAddress(&p, gP_hi);  Phi  = (__nv_bfloat16*)p;
    cudaGetSymbolAddress(&p, gP_lo);  Plo  = (__nv_bfloat16*)p;
    cudaGetSymbolAddress(&p, gE_hi);  Ehi  = (__nv_bfloat16*)p;
    cudaGetSymbolAddress(&p, gE_lo);  Elo  = (__nv_bfloat16*)p;
    cudaGetSymbolAddress(&p, gWpe_hi); WpeH = (__nv_bfloat16*)p;
    cudaGetSymbolAddress(&p, gWpe_lo); WpeL = (__nv_bfloat16*)p;
    cudaGetSymbolAddress(&p, gWpc_hi); WpcH = (__nv_bfloat16*)p;
    cudaGetSymbolAddress(&p, gWpc_lo); WpcL = (__nv_bfloat16*)p;
    cudaGetSymbolAddress(&p, gWa1_hi); Wa1H = (__nv_bfloat16*)p;
    cudaGetSymbolAddress(&p, gWa1_lo); Wa1L = (__nv_bfloat16*)p;
    cudaGetSymbolAddress(&p, gWd1_hi); Wd1H = (__nv_bfloat16*)p;
    cudaGetSymbolAddress(&p, gWd1_lo); Wd1L = (__nv_bfloat16*)p;
    cudaGetSymbolAddress(&p, gWa2_hi); Wa2H = (__nv_bfloat16*)p;
    cudaGetSymbolAddress(&p, gWa2_lo); Wa2L = (__nv_bfloat16*)p;
    cudaGetSymbolAddress(&p, gWd2_hi); Wd2H = (__nv_bfloat16*)p;
    cudaGetSymbolAddress(&p, gWd2_lo); Wd2L = (__nv_bfloat16*)p;
    cudaGetSymbolAddress(&p, gWrc_hi); WrcH = (__nv_bfloat16*)p;
    cudaGetSymbolAddress(&p, gWrc_lo); WrcL = (__nv_bfloat16*)p;

    // pad columns of Xc
    pad_xc<<<N_REL, 64>>>(Xchi, Xclo);
    combine_bias<<<1, 64>>>(b_rel, b_ctx, bias_rc);

    // weight transpose-conversions (64x64 tiles, vectorized)
    conv_T_hl<<<dim3(8, 16), 256>>>(w_post_emb, 512, 1024, WpeH, WpeL, 512);
    conv_T_hl<<<dim3(16, 64), 256>>>(w_post_cat, 1024, 4096, WpcH, WpcL, 1024);
    conv_T_hl<<<dim3(64, 7), 256>>>(w_attn1, 4096, 400, Wa1H, Wa1L, 4096);
    conv_T_hl<<<dim3(68, 64), 256>>>(w_dr1, KCAT, 4096, Wd1H, Wd1L, KCATP);
    conv_T_hl<<<dim3(64, 7), 256>>>(w_attn2, 4096, 400, Wa2H, Wa2L, 4096);
    conv_T_hl<<<dim3(68, 64), 256>>>(w_dr2, KCAT, 4096, Wd2H, Wd2L, KCATP);
    conv_T_hl<<<dim3(64, 1), 256>>>(w_rel, 4096, 51, WrcH, WrcL, KRC);
    conv_T_hl<<<dim3(16, 1), 256>>>(w_ctx, 1024, 51, WrcH + 4096, WrcL + 4096, KRC);

    // 1) edge_rep = edge_ctx @ w_post_emb + b
    conv_rows(edge_ctx, 512, Ehi, Elo, 512, N_OBJ);
    hm_gemm<EPI_BIAS,0><<<dim3(1024/128, N_OBJ/128), 128, HM_DSMEM>>>(
        Ehi, Elo, 512, WpeH, WpeL, 512, b_post_emb, nullptr, 0,
        edge_rep, 1024, nullptr, nullptr, 0, 1024, 512, HM_NOEXTRA);

    // 2) gather + split -> P hi/lo
    gather_hl<<<N_REL, 256>>>(edge_rep, rel_pairs, Phi, Plo);

    // 3) x_local = relu(union * (P @ Wpc + b)) -> Xc cols [200,4296);
    //    fused: union hi/lo split -> U (input of attn1)
    hm_gemm<EPI_MULRELU,1><<<dim3(POOL/128, N_REL/128), 128, HM_DSMEM>>>(
        Phi, Plo, 1024, WpcH, WpcL, 1024, b_post_cat, union_feat, POOL,
        nullptr, 0, Xchi + 200, Xclo + 200, KCATP, POOL, 1024,
        nullptr, nullptr, nullptr, nullptr, nullptr, 0, (1 << 30), Uhi, Ulo);

    // 4) LRGA-1 on union_features
    hm_gemm<EPI_RELU,0><<<dim3(512/128, N_REL/128), 128, HM_DSMEM>>>(
        Uhi, Ulo, POOL, Wa1H, Wa1L, POOL, b_attn1, nullptr, 0,
        tmp, 400, nullptr, nullptr, 0, 400, POOL, HM_NOEXTRA);
    lrga_part<<<64, 320>>>(tmp, 400, cs_part, vz_part, N_REL);
    lrga_finish<<<1, 256>>>(cs_part, usvs, dscale);
    vtz_reduce<<<40, 256>>>(vz_part, vtz);
    gemm_scalerelu_hl<<<dim3(1, N_REL/128), 256>>>(
        tmp, 400, vtz, 100, dscale, Xchi, Xclo, KCATP, N_REL, 100, 100);

    // 5) x = GN(relu(Xc @ Wd1 + b))
    hm_gemm<EPI_RELU,0><<<dim3(POOL/128, N_REL/128), 128, HM_DSMEM>>>(
        Xchi, Xclo, KCATP, Wd1H, Wd1L, KCATP, b_dr1, nullptr, 0,
        ybuf, POOL, nullptr, nullptr, 0, POOL, KCATP, HM_NOEXTRA);
    groupnorm_hl<<<N_REL, 256>>>(ybuf, gn_gamma, gn_beta, Uhi, Ulo, Xchi, Xclo);

    // 6) LRGA-2 on x
    hm_gemm<EPI_RELU,0><<<dim3(512/128, N_REL/128), 128, HM_DSMEM>>>(
        Uhi, Ulo, POOL, Wa2H, Wa2L, POOL, b_attn2, nullptr, 0,
        tmp, 400, nullptr, nullptr, 0, 400, POOL, HM_NOEXTRA);
    lrga_part<<<64, 320>>>(tmp, 400, cs_part, vz_part, N_REL);
    lrga_finish<<<1, 256>>>(cs_part, usvs, dscale);
    vtz_reduce<<<40, 256>>>(vz_part, vtz);
    gemm_scalerelu_hl<<<dim3(1, N_REL/128), 256>>>(
        tmp, 400, vtz, 100, dscale, Xchi, Xclo, KCATP, N_REL, 100, 100);

    // 7) visual = Xc @ Wd2 + b -> U hi/lo
    hm_gemm<EPI_BIAS,1><<<dim3(POOL/128, N_REL/128), 128, HM_DSMEM>>>(
        Xchi, Xclo, KCATP, Wd2H, Wd2L, KCATP, b_dr2, nullptr, 0,
        nullptr, 0, Uhi, Ulo, POOL, POOL, KCATP, HM_NOEXTRA);

    // 8) merged output: rel_dists = [visual | P] @ WrcT + (b_rel+b_ctx) + freq
    hm_gemm<EPI_BIASFREQ,0><<<dim3(1, N_REL/128), 128, HM_DSMEM>>>(
        Uhi, Ulo, POOL, WrcH, WrcL, KRC, bias_rc, nullptr, 0,
        out, NUM_REL, nullptr, nullptr, 0, NUM_REL, KRC,
        rel_pairs, obj_preds, freq_table,
        Phi, Plo, 1024, 4096, nullptr, nullptr);
}

// round 15
// speedup vs baseline: 1.0157x; 1.0157x over previous
#include <cuda_runtime.h>
#include <cuda_bf16.h>
#include <cstdint>

// ---------------------------------------------------------------------------
// Problem constants
// ---------------------------------------------------------------------------
#define HID 512
#define POOL 4096
#define NUM_OBJ 151
#define NUM_REL 51
#define KLR 100
#define N_OBJ 4096
#define N_REL 16384
#define KCAT (2*KLR + POOL)   // 4296
#define KCATP 4352            // padded to 64
#define KRC 5120              // merged output GEMM K: 4096 (visual) + 1024 (P)

// ---------------------------------------------------------------------------
// Scratch (device globals; no allocation allowed)
// ---------------------------------------------------------------------------
__device__ float g_edge_rep[(size_t)N_OBJ * 1024];
__device__ float g_tmp[(size_t)N_REL * 400];
__device__ float g_y[(size_t)N_REL * POOL];
__device__ float g_colsum_part[64 * 200];
__device__ float g_usvs[200];
__device__ float g_vtz_part[64 * 10000];
__device__ float g_vtz[10000];
__device__ float g_dscale[1];
__device__ float g_bias_rc[64];

// bf16 hi/lo activation buffers
__device__ __nv_bfloat16 gU_hi[(size_t)N_REL * POOL];
__device__ __nv_bfloat16 gU_lo[(size_t)N_REL * POOL];
__device__ __nv_bfloat16 gXc_hi[(size_t)N_REL * KCATP];
__device__ __nv_bfloat16 gXc_lo[(size_t)N_REL * KCATP];
__device__ __nv_bfloat16 gP_hi[(size_t)N_REL * 1024];
__device__ __nv_bfloat16 gP_lo[(size_t)N_REL * 1024];
__device__ __nv_bfloat16 gE_hi[(size_t)N_OBJ * 512];
__device__ __nv_bfloat16 gE_lo[(size_t)N_OBJ * 512];
// bf16 hi/lo weights (transposed to [N, Kpad])
__device__ __nv_bfloat16 gWpe_hi[1024 * 512],  gWpe_lo[1024 * 512];
__device__ __nv_bfloat16 gWpc_hi[4096 * 1024], gWpc_lo[4096 * 1024];
__device__ __nv_bfloat16 gWa1_hi[512 * 4096],  gWa1_lo[512 * 4096];
__device__ __nv_bfloat16 gWd1_hi[(size_t)4096 * KCATP], gWd1_lo[(size_t)4096 * KCATP];
__device__ __nv_bfloat16 gWa2_hi[512 * 4096],  gWa2_lo[512 * 4096];
__device__ __nv_bfloat16 gWd2_hi[(size_t)4096 * KCATP], gWd2_lo[(size_t)4096 * KCATP];
__device__ __nv_bfloat16 gWrc_hi[(size_t)128 * KRC], gWrc_lo[(size_t)128 * KRC];

// ---------------------------------------------------------------------------
// PTX helpers (plain sm_80+ PTX — harness ptxas targets bare sm_103)
// ---------------------------------------------------------------------------
__device__ __forceinline__ uint32_t s2u(const void* p) {
    uint32_t a;
    asm("{ .reg .u64 t; cvta.to.shared.u64 t, %1; cvt.u32.u64 %0, t; }" : "=r"(a) : "l"(p));
    return a;
}
#define CP_ASYNC16(dst, src) \
    asm volatile("cp.async.cg.shared.global [%0], [%1], 16;" :: "r"(dst), "l"(src))
#define CP_COMMIT() asm volatile("cp.async.commit_group;" ::: "memory")
#define CP_WAIT1()  asm volatile("cp.async.wait_group 1;" ::: "memory")

__device__ __forceinline__ void ldsm4(uint32_t* r, uint32_t addr) {
    asm volatile("ldmatrix.sync.aligned.m8n8.x4.shared.b16 {%0,%1,%2,%3}, [%4];"
        : "=r"(r[0]), "=r"(r[1]), "=r"(r[2]), "=r"(r[3]) : "r"(addr));
}
__device__ __forceinline__ void mma_bf16(float* d, const uint32_t* a, const uint32_t* b) {
    asm volatile(
        "mma.sync.aligned.m16n8k16.row.col.f32.bf16.bf16.f32 "
        "{%0,%1,%2,%3}, {%4,%5,%6,%7}, {%8,%9}, {%0,%1,%2,%3};"
        : "+f"(d[0]), "+f"(d[1]), "+f"(d[2]), "+f"(d[3])
        : "r"(a[0]), "r"(a[1]), "r"(a[2]), "r"(a[3]), "r"(b[0]), "r"(b[1]));
}

__device__ __forceinline__ void split_hl(float v, __nv_bfloat16& h, __nv_bfloat16& l) {
    h = __float2bfloat16(v);
    l = __float2bfloat16(v - __bfloat162float(h));
}

// XOR-swizzled smem layout: row r (0..127), 16B-chunk c (0..3); 64B rows.
__device__ __forceinline__ uint32_t swz(uint32_t r, uint32_t c) {
    return r * 64u + ((c ^ ((r >> 1) & 3u)) << 4);
}

// ---------------------------------------------------------------------------
// HMMA GEMM: C = epi(A @ B^T), hi/lo bf16 3-pass fp32 emulation.
// 128x128 tile, BK=32, 128 threads (4 warps, each 64x64).
// 3-stage cp.async pipeline, ONE __syncthreads per K-chunk, 2 CTAs/SM.
// (R13 core — R14's B double-buffering regressed via register pressure.)
// Supports dual-source A (Ksplit) for the merged output GEMM.
// ---------------------------------------------------------------------------
#define EPI_BIAS      0
#define EPI_RELU      1
#define EPI_MULRELU   2   // OUT=1: also splits 'extra' into Euhi/Eulo
#define EPI_BIASFREQ  5   // C = v + bias[col] + freq[(p0*NUM_OBJ+p1)*NUM_REL+col]
// OUT: 0 = fp32 C;  1 = bf16 hi/lo pair (Dhi/Dlo)

#define MAT_BYTES 8192u                    // 128 rows x 64B
#define STAGE_BYTES (4u * MAT_BYTES)       // 32768
#define HM_DSMEM (3 * 32768)               // 98304 -> 2 CTAs/SM

__device__ __forceinline__ void hm_load_stage(
    uint32_t st, int t,
    const __nv_bfloat16* __restrict__ Ahi, const __nv_bfloat16* __restrict__ Alo,
    int lda, int bm0,
    const __nv_bfloat16* __restrict__ Bhi, const __nv_bfloat16* __restrict__ Blo,
    int ldb, int bn0, int k0,
    const __nv_bfloat16* __restrict__ A2hi, const __nv_bfloat16* __restrict__ A2lo,
    int lda2, int Ksplit)
{
    const __nv_bfloat16* sAh = Ahi;
    const __nv_bfloat16* sAl = Alo;
    int sLda = lda, scol = k0;
    if (k0 >= Ksplit) { sAh = A2hi; sAl = A2lo; sLda = lda2; scol = k0 - Ksplit; }
#pragma unroll
    for (int i = 0; i < 4; i++) {
        int q = t + (i << 7);                 // 512 quads
        uint32_t r = (uint32_t)(q >> 2), c = (uint32_t)(q & 3);
        uint32_t dst = st + swz(r, c);
        int acol = scol + (int)c * 8;
        int bcol = k0 + (int)c * 8;
        CP_ASYNC16(dst,                   sAh + (size_t)(bm0 + (int)r) * sLda + acol);
        CP_ASYNC16(dst + MAT_BYTES,       sAl + (size_t)(bm0 + (int)r) * sLda + acol);
        CP_ASYNC16(dst + 2u * MAT_BYTES,  Bhi + (size_t)(bn0 + (int)r) * ldb + bcol);
        CP_ASYNC16(dst + 3u * MAT_BYTES,  Blo + (size_t)(bn0 + (int)r) * ldb + bcol);
    }
}

template<int EPI>
__device__ __forceinline__ float hm_epi(float v, int row, int col,
    const float* __restrict__ bias, const float* __restrict__ extra, int lde,
    const float* __restrict__ C, int ldc,
    const float* __restrict__ freq_row)
{
    if (EPI == EPI_BIAS)         return v + bias[col];
    else if (EPI == EPI_RELU)    return fmaxf(v + bias[col], 0.f);
    else if (EPI == EPI_MULRELU) return fmaxf(extra[(size_t)row * lde + col] * (v + bias[col]), 0.f);
    else                         return v + bias[col] + freq_row[col];
}

template<int EPI, int OUT>
__global__ void __launch_bounds__(128, 2)
hm_gemm(const __nv_bfloat16* __restrict__ Ahi, const __nv_bfloat16* __restrict__ Alo, int lda,
        const __nv_bfloat16* __restrict__ Bhi, const __nv_bfloat16* __restrict__ Blo, int ldb,
        const float* __restrict__ bias, const float* __restrict__ extra, int lde,
        float* __restrict__ C, int ldc,
        __nv_bfloat16* __restrict__ Dhi, __nv_bfloat16* __restrict__ Dlo, int ldd,
        int ncols, int K,
        const int* __restrict__ pairs, const int* __restrict__ obj_preds,
        const float* __restrict__ freq,
        const __nv_bfloat16* __restrict__ A2hi, const __nv_bfloat16* __restrict__ A2lo,
        int lda2, int Ksplit,
        __nv_bfloat16* __restrict__ Euhi, __nv_bfloat16* __restrict__ Eulo)
{
    extern __shared__ char dsm[];
    const uint32_t sb = s2u(dsm);
    const int t = threadIdx.x, w = t >> 5, l = t & 31;
    const int bm0 = blockIdx.y * 128, bn0 = blockIdx.x * 128;
    const int wm = (w >> 1) * 64, wn = (w & 1) * 64;   // 2x2 warp grid, 64x64 each

    const uint32_t a_row = (uint32_t)(((l >> 3) & 1) * 8 + (l & 7));
    const uint32_t a_ch  = (uint32_t)(l >> 4);
    const uint32_t b_row = (uint32_t)((l >> 4) * 8 + (l & 7));
    const uint32_t b_ch  = (uint32_t)((l >> 3) & 1);

    float acc[4][8][4];
#pragma unroll
    for (int i = 0; i < 4; i++)
#pragma unroll
        for (int j = 0; j < 8; j++)
#pragma unroll
            for (int q = 0; q < 4; q++) acc[i][j][q] = 0.f;

    const int nk = K >> 5;
    hm_load_stage(sb, t, Ahi, Alo, lda, bm0, Bhi, Blo, ldb, bn0, 0,
                  A2hi, A2lo, lda2, Ksplit);
    CP_COMMIT();
    hm_load_stage(sb + STAGE_BYTES, t, Ahi, Alo, lda, bm0, Bhi, Blo, ldb, bn0, 32,
                  A2hi, A2lo, lda2, Ksplit);
    CP_COMMIT();

    for (int j = 0; j < nk; j++) {
        CP_WAIT1();
        __syncthreads();                       // single barrier per chunk
        if (j + 2 < nk)
            hm_load_stage(sb + (uint32_t)((j + 2) % 3) * STAGE_BYTES, t,
                          Ahi, Alo, lda, bm0, Bhi, Blo, ldb, bn0, (j + 2) * 32,
                          A2hi, A2lo, lda2, Ksplit);
        CP_COMMIT();

        uint32_t st = sb + (uint32_t)(j % 3) * STAGE_BYTES;
#pragma unroll
        for (int ks = 0; ks < 2; ks++) {
            const uint32_t kc = (uint32_t)ks * 2u;
            uint32_t Ah[4][4], Al[4][4];
#pragma unroll
            for (int mi = 0; mi < 4; mi++)
                ldsm4(Ah[mi], st + swz((uint32_t)(wm + mi * 16) + a_row, kc + a_ch));
#pragma unroll
            for (int mi = 0; mi < 4; mi++)
                ldsm4(Al[mi], st + MAT_BYTES + swz((uint32_t)(wm + mi * 16) + a_row, kc + a_ch));
#pragma unroll
            for (int nj = 0; nj < 4; nj++) {
                uint32_t Bh[4], Bl[4];
                ldsm4(Bh, st + 2u * MAT_BYTES + swz((uint32_t)(wn + nj * 16) + b_row, kc + b_ch));
                ldsm4(Bl, st + 3u * MAT_BYTES + swz((uint32_t)(wn + nj * 16) + b_row, kc + b_ch));
#pragma unroll
                for (int mi = 0; mi < 4; mi++) {
                    mma_bf16(acc[mi][nj * 2 + 0], Ah[mi], &Bh[0]);
                    mma_bf16(acc[mi][nj * 2 + 1], Ah[mi], &Bh[2]);
                }
#pragma unroll
                for (int mi = 0; mi < 4; mi++) {
                    mma_bf16(acc[mi][nj * 2 + 0], Ah[mi], &Bl[0]);
                    mma_bf16(acc[mi][nj * 2 + 1], Ah[mi], &Bl[2]);
                }
#pragma unroll
                for (int mi = 0; mi < 4; mi++) {
                    mma_bf16(acc[mi][nj * 2 + 0], Al[mi], &Bh[0]);
                    mma_bf16(acc[mi][nj * 2 + 1], Al[mi], &Bh[2]);
                }
            }
        }
    }

    // epilogue
    const int rl = l >> 2, cl = (l & 3) * 2;
    const bool ldc_even = ((ldc & 1) == 0);
#pragma unroll
    for (int mi = 0; mi < 4; mi++) {
#pragma unroll
        for (int ni = 0; ni < 8; ni++) {
            int row0 = bm0 + wm + mi * 16 + rl;
            int col0 = bn0 + wn + ni * 8 + cl;
#pragma unroll
            for (int h = 0; h < 2; h++) {
                int row = row0 + h * 8;
                float v0 = acc[mi][ni][h * 2 + 0];
                float v1 = acc[mi][ni][h * 2 + 1];
                const float* freq_row = nullptr;
                if (EPI == EPI_BIASFREQ) {
                    int p0 = obj_preds[pairs[2 * row]];
                    int p1 = obj_preds[pairs[2 * row + 1]];
                    freq_row = freq + ((size_t)p0 * NUM_OBJ + p1) * NUM_REL;
                }
                if (OUT == 1) {
                    if (col0 + 1 < ncols) {
                        float o0, o1;
                        if (EPI == EPI_MULRELU) {
                            float2 e = *(const float2*)(extra + (size_t)row * lde + col0);
                            o0 = fmaxf(e.x * (v0 + bias[col0]), 0.f);
                            o1 = fmaxf(e.y * (v1 + bias[col0 + 1]), 0.f);
                            __nv_bfloat16 uh0, ul0, uh1, ul1;
                            split_hl(e.x, uh0, ul0); split_hl(e.y, uh1, ul1);
                            __nv_bfloat162 pu; pu.x = uh0; pu.y = uh1;
                            __nv_bfloat162 qu; qu.x = ul0; qu.y = ul1;
                            *(__nv_bfloat162*)(Euhi + (size_t)row * lde + col0) = pu;
                            *(__nv_bfloat162*)(Eulo + (size_t)row * lde + col0) = qu;
                        } else {
                            o0 = hm_epi<EPI>(v0, row, col0,     bias, extra, lde, C, ldc, freq_row);
                            o1 = hm_epi<EPI>(v1, row, col0 + 1, bias, extra, lde, C, ldc, freq_row);
                        }
                        __nv_bfloat16 h0, l0, h1, l1;
                        split_hl(o0, h0, l0); split_hl(o1, h1, l1);
                        __nv_bfloat162 ph; ph.x = h0; ph.y = h1;
                        __nv_bfloat162 pl; pl.x = l0; pl.y = l1;
                        *(__nv_bfloat162*)(Dhi + (size_t)row * ldd + col0) = ph;
                        *(__nv_bfloat162*)(Dlo + (size_t)row * ldd + col0) = pl;
                    }
                } else if (ldc_even && col0 + 1 < ncols) {
                    float2 o;
                    o.x = hm_epi<EPI>(v0, row, col0,     bias, extra, lde, C, ldc, freq_row);
                    o.y = hm_epi<EPI>(v1, row, col0 + 1, bias, extra, lde, C, ldc, freq_row);
                    *(float2*)(C + (size_t)row * ldc + col0) = o;
                } else {
                    if (col0 < ncols)
                        C[(size_t)row * ldc + col0] =
                            hm_epi<EPI>(v0, row, col0, bias, extra, lde, C, ldc, freq_row);
                    if (col0 + 1 < ncols)
                        C[(size_t)row * ldc + col0 + 1] =
                            hm_epi<EPI>(v1, row, col0 + 1, bias, extra, lde, C, ldc, freq_row);
                }
            }
        }
    }
}

// ---------------------------------------------------------------------------
// Conversions
// ---------------------------------------------------------------------------
__global__ void conv_hl(const float* __restrict__ in, int C,
                        __nv_bfloat16* __restrict__ hi, __nv_bfloat16* __restrict__ lo,
                        int Cpad, long total4)
{
    long i = (long)blockIdx.x * blockDim.x + threadIdx.x;
    if (i >= total4) return;
    long e = i * 4;
    long r = e / Cpad;
    int c = (int)(e - r * Cpad);
    float4 v;
    if (c < C) v = *(const float4*)(in + r * C + c);
    else { v.x = v.y = v.z = v.w = 0.f; }
    __nv_bfloat16 h[4], l[4];
    split_hl(v.x, h[0], l[0]); split_hl(v.y, h[1], l[1]);
    split_hl(v.z, h[2], l[2]); split_hl(v.w, h[3], l[3]);
    *(uint2*)(hi + e) = *(uint2*)h;
    *(uint2*)(lo + e) = *(uint2*)l;
}

// [K,N] fp32 -> transposed [N,Kpad] hi/lo bf16; 64x64 tiles, vectorized stores.
__global__ void __launch_bounds__(256)
conv_T_hl(const float* __restrict__ in, int K, int N,
          __nv_bfloat16* __restrict__ hi, __nv_bfloat16* __restrict__ lo,
          int Kpad)
{
    __shared__ float tile[64][65];
    const int k0 = blockIdx.x * 64, n0 = blockIdx.y * 64;
    const int t = threadIdx.x;
    const int tn = t & 63, tk = t >> 6;
#pragma unroll
    for (int q = 0; q < 16; q++) {
        int k = k0 + tk + q * 4, n = n0 + tn;
        tile[tk + q * 4][tn] = (k < K && n < N) ? in[(size_t)k * N + n] : 0.f;
    }
    __syncthreads();
    const int kg = t & 15;
    const int nr = t >> 4;
#pragma unroll
    for (int q = 0; q < 4; q++) {
        int nrow = n0 + nr + q * 16;
        int kc = k0 + kg * 4;
        if (nrow < N && kc < Kpad) {
            __nv_bfloat16 h[4], l[4];
#pragma unroll
            for (int e = 0; e < 4; e++)
                split_hl(tile[kg * 4 + e][nr + q * 16], h[e], l[e]);
            *(uint2*)(hi + (size_t)nrow * Kpad + kc) = *(uint2*)h;
            *(uint2*)(lo + (size_t)nrow * Kpad + kc) = *(uint2*)l;
        }
    }
}

// zero the 56 pad columns of the Xc slab
__global__ void pad_xc(__nv_bfloat16* __restrict__ hi, __nv_bfloat16* __restrict__ lo)
{
    int row = blockIdx.x, c = threadIdx.x;
    if (c < KCATP - KCAT) {
        size_t idx = (size_t)row * KCATP + KCAT + c;
        hi[idx] = __float2bfloat16(0.f);
        lo[idx] = __float2bfloat16(0.f);
    }
}

__global__ void combine_bias(const float* __restrict__ b_rel,
                             const float* __restrict__ b_ctx,
                             float* __restrict__ out)
{
    int c = threadIdx.x;
    if (c < NUM_REL) out[c] = b_rel[c] + b_ctx[c];
    else if (c < 64) out[c] = 0.f;
}

// fused gather + hi/lo split
__global__ void gather_hl(const float* __restrict__ edge_rep,
                          const int* __restrict__ pairs,
                          __nv_bfloat16* __restrict__ Phi,
                          __nv_bfloat16* __restrict__ Plo)
{
    int i = blockIdx.x;
    int s = pairs[2 * i], o = pairs[2 * i + 1];
    for (int c4 = threadIdx.x; c4 < 256; c4 += blockDim.x) {
        const float4* src = (c4 < 128)
            ? (const float4*)(edge_rep + (size_t)s * 1024) + c4
            : (const float4*)(edge_rep + (size_t)o * 1024 + 512) + (c4 - 128);
        float4 v = *src;
        __nv_bfloat16 h[4], l[4];
        split_hl(v.x, h[0], l[0]); split_hl(v.y, h[1], l[1]);
        split_hl(v.z, h[2], l[2]); split_hl(v.w, h[3], l[3]);
        size_t e = (size_t)i * 1024 + c4 * 4;
        *(uint2*)(Phi + e) = *(uint2*)h;
        *(uint2*)(Plo + e) = *(uint2*)l;
    }
}

// ---------------------------------------------------------------------------
// fp32 FFMA2 GEMM for tiny u@vtz -> Xc cols [0,100); fused t-copy -> [100,200)
// ---------------------------------------------------------------------------
typedef unsigned long long u64;
__device__ __forceinline__ u64 pack2(float lo, float hi) {
    u64 r; asm("mov.b64 %0, {%1,%2};" : "=l"(r) : "f"(lo), "f"(hi)); return r;
}
__device__ __forceinline__ float2 unpack2(u64 v) {
    float2 r; asm("mov.b64 {%0,%1}, %2;" : "=f"(r.x), "=f"(r.y) : "l"(v)); return r;
}
__device__ __forceinline__ void fma2(u64 &c, u64 a, u64 b) {
    asm("fma.rn.f32x2 %0, %1, %2, %3;" : "=l"(c) : "l"(a), "l"(b), "l"(c));
}

__global__ void __launch_bounds__(256, 2)
gemm_scalerelu_hl(const float* __restrict__ A, int lda,
                  const float* __restrict__ B, int ldb,
                  const float* __restrict__ dscale_ptr,
                  __nv_bfloat16* __restrict__ Dhi, __nv_bfloat16* __restrict__ Dlo,
                  int ldd, int M, int N, int K)
{
    __shared__ __align__(16) float As[8][132];
    __shared__ __align__(16) float Bs[8][128];
    const int t = threadIdx.x;
    const int tx = t & 15, ty = t >> 4;
    const int bn0 = blockIdx.x * 128, bm0 = blockIdx.y * 128;
    const int a_m = t >> 1, a_k = (t & 1) * 4;
    const int b_k = t >> 5, b_n = (t & 31) * 4;
    u64 acc[8][4];
#pragma unroll
    for (int i = 0; i < 8; i++)
#pragma unroll
        for (int j = 0; j < 4; j++) acc[i][j] = 0ull;
    for (int k0 = 0; k0 < K; k0 += 8) {
#pragma unroll
        for (int q = 0; q < 4; q++) {
            int kk = k0 + a_k + q, rr = bm0 + a_m;
            As[a_k + q][a_m] = (rr < M && kk < K) ? A[(size_t)rr * lda + kk] : 0.f;
        }
#pragma unroll
        for (int q = 0; q < 4; q++) {
            int nn = bn0 + b_n + q, kk = k0 + b_k;
            Bs[b_k][b_n + q] = (kk < K && nn < N) ? B[(size_t)kk * ldb + nn] : 0.f;
        }
        __syncthreads();
#pragma unroll
        for (int kk = 0; kk < 8; kk++) {
            float4 a0 = *(const float4*)&As[kk][ty * 8];
            float4 a1 = *(const float4*)&As[kk][ty * 8 + 4];
            u64 b2[4];
            *(ulonglong2*)&b2[0] = *(const ulonglong2*)&Bs[kk][tx * 8];
            *(ulonglong2*)&b2[2] = *(const ulonglong2*)&Bs[kk][tx * 8 + 4];
            float af[8] = {a0.x, a0.y, a0.z, a0.w, a1.x, a1.y, a1.z, a1.w};
#pragma unroll
            for (int i = 0; i < 8; i++) {
                u64 a2 = pack2(af[i], af[i]);
                fma2(acc[i][0], a2, b2[0]); fma2(acc[i][1], a2, b2[1]);
                fma2(acc[i][2], a2, b2[2]); fma2(acc[i][3], a2, b2[3]);
            }
        }
        __syncthreads();
    }
    float d = *dscale_ptr;
#pragma unroll
    for (int i = 0; i < 8; i++) {
        int row = bm0 + ty * 8 + i;
        if (row >= M) continue;
#pragma unroll
        for (int jj = 0; jj < 4; jj++) {
            float2 v = unpack2(acc[i][jj]);
            int c0 = bn0 + tx * 8 + jj * 2;
            if (c0 + 1 < N) {
                __nv_bfloat16 h0, l0, h1, l1;
                split_hl(fmaxf(v.x * d, 0.f), h0, l0);
                split_hl(fmaxf(v.y * d, 0.f), h1, l1);
                __nv_bfloat162 ph; ph.x = h0; ph.y = h1;
                __nv_bfloat162 pl; pl.x = l0; pl.y = l1;
                *(__nv_bfloat162*)(Dhi + (size_t)row * ldd + c0) = ph;
                *(__nv_bfloat162*)(Dlo + (size_t)row * ldd + c0) = pl;
            }
        }
    }
    // fused copy of t-part (tmp cols [300,400), already relu'd) -> Xc cols [100,200)
    for (int idx = t; idx < 128 * 100; idx += 256) {
        int r = idx / 100, c = idx % 100;
        int row = bm0 + r;
        if (row < M) {
            float v = A[(size_t)row * lda + 300 + c];
            __nv_bfloat16 h, l;
            split_hl(v, h, l);
            size_t o = (size_t)row * ldd + 100 + c;
            Dhi[o] = h; Dlo[o] = l;
        }
    }
}

// ---------------------------------------------------------------------------
// Fused LRGA reductions: colsum partials + vtz partials in ONE pass over tmp.
// ---------------------------------------------------------------------------
__global__ void __launch_bounds__(320)
lrga_part(const float* __restrict__ tmp, int ld,
          float* __restrict__ cs_part, float* __restrict__ vz_part, int M)
{
    __shared__ float sval[304];
    int t = threadIdx.x;
    int a_base = (t % 20) * 5;
    int b_base = (t / 20) * 10;
    float csum = 0.f;
    float acc[50];
#pragma unroll
    for (int q = 0; q < 50; q++) acc[q] = 0.f;

    for (int r = blockIdx.x; r < M; r += gridDim.x) {
        if (t < 300) sval[t] = tmp[(size_t)r * ld + t];
        __syncthreads();
        if (t < 200) {
            csum += sval[t];
            float zr[10];
#pragma unroll
            for (int j = 0; j < 10; j++) zr[j] = sval[200 + b_base + j];
#pragma unroll
            for (int ia = 0; ia < 5; ia++) {
                float va = sval[100 + a_base + ia];
#pragma unroll
                for (int j = 0; j < 10; j++) acc[ia * 10 + j] += va * zr[j];
            }
        }
        __syncthreads();
    }
    if (t < 200) {
        cs_part[blockIdx.x * 200 + t] = csum;
#pragma unroll
        for (int ia = 0; ia < 5; ia++)
#pragma unroll
            for (int j = 0; j < 10; j++)
                vz_part[(size_t)blockIdx.x * 10000 + (a_base + ia) * 100 + b_base + j] = acc[ia * 10 + j];
    }
}

// Merged second-stage: blocks 0..39 reduce vz_part -> vtz; block 40 reduces
// cs_part -> usvs and computes dscale. The two jobs read disjoint inputs.
__global__ void lrga_reduce2(const float* __restrict__ vz_part, float* __restrict__ vtz,
                             const float* __restrict__ cs_part,
                             float* __restrict__ usvs, float* __restrict__ dout)
{
    int t = threadIdx.x;
    if (blockIdx.x < 40) {
        int idx = blockIdx.x * 256 + t;
        if (idx >= 10000) return;
        float s = 0.f;
        for (int b = 0; b < 64; b++) s += vz_part[(size_t)b * 10000 + idx];
        vtz[idx] = s;
    } else {
        __shared__ float red[128];
        float s = 0.f;
        if (t < 200) {
            for (int b = 0; b < 64; b++) s += cs_part[b * 200 + t];
            usvs[t] = s;
        }
        __syncthreads();
        float v = (t < 100) ? usvs[t] * usvs[100 + t] : 0.f;
        if (t < 128) red[t] = v;
        __syncthreads();
        for (int st = 64; st > 0; st >>= 1) {
            if (t < st) red[t] += red[t + st];
            __syncthreads();
        }
        if (t == 0) dout[0] = 1.f / (red[0] / (float)N_REL + 1e-6f);
    }
}

__global__ void groupnorm_hl(const float* __restrict__ y,
                             const float* __restrict__ gamma,
                             const float* __restrict__ beta,
                             __nv_bfloat16* __restrict__ Uhi,
                             __nv_bfloat16* __restrict__ Ulo,
                             __nv_bfloat16* __restrict__ Xchi,
                             __nv_bfloat16* __restrict__ Xclo)
{
    int row = blockIdx.x;
    int w = threadIdx.x >> 5, l = threadIdx.x & 31;
    const float* p = y + (size_t)row * POOL + w * 512;
    float vals[16];
    float s = 0.f, ss = 0.f;
#pragma unroll
    for (int i = 0; i < 16; i++) {
        float v = p[l + i * 32];
        vals[i] = v; s += v; ss += v * v;
    }
#pragma unroll
    for (int off = 16; off > 0; off >>= 1) {
        s  += __shfl_xor_sync(0xffffffffu, s,  off);
        ss += __shfl_xor_sync(0xffffffffu, ss, off);
    }
    float mean = s * (1.f / 512.f);
    float var  = fmaxf(ss * (1.f / 512.f) - mean * mean, 0.f);
    float rstd = rsqrtf(var + 1e-5f);
#pragma unroll
    for (int i = 0; i < 16; i++) {
        int c = w * 512 + l + i * 32;
        float xn = (vals[i] - mean) * rstd * gamma[c] + beta[c];
        __nv_bfloat16 h, lo_;
        split_hl(xn, h, lo_);
        size_t ui = (size_t)row * POOL + c;
        Uhi[ui] = h; Ulo[ui] = lo_;
        float r = fmaxf(xn, 0.f);
        split_hl(r, h, lo_);
        size_t xi = (size_t)row * KCATP + 200 + c;
        Xchi[xi] = h; Xclo[xi] = lo_;
    }
}

// ---------------------------------------------------------------------------
// Launch
// ---------------------------------------------------------------------------
static inline void conv_rows(const float* in, int C, __nv_bfloat16* hi, __nv_bfloat16* lo,
                             int Cpad, long R)
{
    long total4 = R * Cpad / 4;
    conv_hl<<<(unsigned)((total4 + 255) / 256), 256>>>(in, C, hi, lo, Cpad, total4);
}

#define HM_NOEXTRA nullptr, nullptr, nullptr, nullptr, nullptr, 0, (1 << 30), nullptr, nullptr

extern "C" void kernel_launch(void* const* d_in, const int* in_sizes, int n_in,
                              void* d_out, int out_size)
{
    const float* edge_ctx   = (const float*)d_in[0];
    const float* union_feat = (const float*)d_in[1];
    const int*   rel_pairs  = (const int*)  d_in[2];
    const int*   obj_preds  = (const int*)  d_in[3];
    const float* w_post_emb = (const float*)d_in[4];
    const float* b_post_emb = (const float*)d_in[5];
    const float* w_post_cat = (const float*)d_in[6];
    const float* b_post_cat = (const float*)d_in[7];
    const float* w_attn1    = (const float*)d_in[8];
    const float* b_attn1    = (const float*)d_in[9];
    const float* w_dr1      = (const float*)d_in[10];
    const float* b_dr1      = (const float*)d_in[11];
    const float* gn_gamma   = (const float*)d_in[12];
    const float* gn_beta    = (const float*)d_in[13];
    const float* w_attn2    = (const float*)d_in[14];
    const float* b_attn2    = (const float*)d_in[15];
    const float* w_dr2      = (const float*)d_in[16];
    const float* b_dr2      = (const float*)d_in[17];
    const float* w_rel      = (const float*)d_in[18];
    const float* b_rel      = (const float*)d_in[19];
    const float* w_ctx      = (const float*)d_in[20];
    const float* b_ctx      = (const float*)d_in[21];
    const float* freq_table = (const float*)d_in[22];
    float* out = (float*)d_out;

    cudaFuncSetAttribute(hm_gemm<EPI_BIAS,0>,     cudaFuncAttributeMaxDynamicSharedMemorySize, HM_DSMEM);
    cudaFuncSetAttribute(hm_gemm<EPI_BIAS,1>,     cudaFuncAttributeMaxDynamicSharedMemorySize, HM_DSMEM);
    cudaFuncSetAttribute(hm_gemm<EPI_RELU,0>,     cudaFuncAttributeMaxDynamicSharedMemorySize, HM_DSMEM);
    cudaFuncSetAttribute(hm_gemm<EPI_MULRELU,1>,  cudaFuncAttributeMaxDynamicSharedMemorySize, HM_DSMEM);
    cudaFuncSetAttribute(hm_gemm<EPI_BIASFREQ,0>, cudaFuncAttributeMaxDynamicSharedMemorySize, HM_DSMEM);

    void* p;
    cudaGetSymbolAddress(&p, g_edge_rep);    float* edge_rep = (float*)p;
    cudaGetSymbolAddress(&p, g_tmp);         float* tmp      = (float*)p;
    cudaGetSymbolAddress(&p, g_y);           float* ybuf     = (float*)p;
    cudaGetSymbolAddress(&p, g_colsum_part); float* cs_part  = (float*)p;
    cudaGetSymbolAddress(&p, g_usvs);        float* usvs     = (float*)p;
    cudaGetSymbolAddress(&p, g_vtz_part);    float* vz_part  = (float*)p;
    cudaGetSymbolAddress(&p, g_vtz);         float* vtz      = (float*)p;
    cudaGetSymbolAddress(&p, g_dscale);      float* dscale   = (float*)p;
    cudaGetSymbolAddress(&p, g_bias_rc);     float* bias_rc  = (float*)p;

    __nv_bfloat16 *Uhi, *Ulo, *Xchi, *Xclo, *Phi, *Plo, *Ehi, *Elo;
    __nv_bfloat16 *WpeH, *WpeL, *WpcH, *WpcL, *Wa1H, *Wa1L, *Wd1H, *Wd1L;
    __nv_bfloat16 *Wa2H, *Wa2L, *Wd2H, *Wd2L, *WrcH, *WrcL;
    cudaGetSymbolAddress(&p, gU_hi);  Uhi  = (__nv_bfloat16*)p;
    cudaGetSymbolAddress(&p, gU_lo);  Ulo  = (__nv_bfloat16*)p;
    cudaGetSymbolAddress(&p, gXc_hi); Xchi = (__nv_bfloat16*)p;
    cudaGetSymbolAddress(&p, gXc_lo); Xclo = (__nv_bfloat16*)p;
    cudaGetSymbolAddress(&p, gP_hi);  Phi  = (__nv_bfloat16*)p;
    cudaGetSymbolAddress(&p, gP_lo);  Plo  = (__nv_bfloat16*)p;
    cudaGetSymbolAddress(&p, gE_hi);  Ehi  = (__nv_bfloat16*)p;
    cudaGetSymbolAddress(&p, gE_lo);  Elo  = (__nv_bfloat16*)p;
    cudaGetSymbolAddress(&p, gWpe_hi); WpeH = (__nv_bfloat16*)p;
    cudaGetSymbolAddress(&p, gWpe_lo); WpeL = (__nv_bfloat16*)p;
    cudaGetSymbolAddress(&p, gWpc_hi); WpcH = (__nv_bfloat16*)p;
    cudaGetSymbolAddress(&p, gWpc_lo); WpcL = (__nv_bfloat16*)p;
    cudaGetSymbolAddress(&p, gWa1_hi); Wa1H = (__nv_bfloat16*)p;
    cudaGetSymbolAddress(&p, gWa1_lo); Wa1L = (__nv_bfloat16*)p;
    cudaGetSymbolAddress(&p, gWd1_hi); Wd1H = (__nv_bfloat16*)p;
    cudaGetSymbolAddress(&p, gWd1_lo); Wd1L = (__nv_bfloat16*)p;
    cudaGetSymbolAddress(&p, gWa2_hi); Wa2H = (__nv_bfloat16*)p;
    cudaGetSymbolAddress(&p, gWa2_lo); Wa2L = (__nv_bfloat16*)p;
    cudaGetSymbolAddress(&p, gWd2_hi); Wd2H = (__nv_bfloat16*)p;
    cudaGetSymbolAddress(&p, gWd2_lo); Wd2L = (__nv_bfloat16*)p;
    cudaGetSymbolAddress(&p, gWrc_hi); WrcH = (__nv_bfloat16*)p;
    cudaGetSymbolAddress(&p, gWrc_lo); WrcL = (__nv_bfloat16*)p;

    // pad columns of Xc
    pad_xc<<<N_REL, 64>>>(Xchi, Xclo);
    combine_bias<<<1, 64>>>(b_rel, b_ctx, bias_rc);

    // weight transpose-conversions (64x64 tiles, vectorized)
    conv_T_hl<<<dim3(8, 16), 256>>>(w_post_emb, 512, 1024, WpeH, WpeL, 512);
    conv_T_hl<<<dim3(16, 64), 256>>>(w_post_cat, 1024, 4096, WpcH, WpcL, 1024);
    conv_T_hl<<<dim3(64, 7), 256>>>(w_attn1, 4096, 400, Wa1H, Wa1L, 4096);
    conv_T_hl<<<dim3(68, 64), 256>>>(w_dr1, KCAT, 4096, Wd1H, Wd1L, KCATP);
    conv_T_hl<<<dim3(64, 7), 256>>>(w_attn2, 4096, 400, Wa2H, Wa2L, 4096);
    conv_T_hl<<<dim3(68, 64), 256>>>(w_dr2, KCAT, 4096, Wd2H, Wd2L, KCATP);
    conv_T_hl<<<dim3(64, 1), 256>>>(w_rel, 4096, 51, WrcH, WrcL, KRC);
    conv_T_hl<<<dim3(16, 1), 256>>>(w_ctx, 1024, 51, WrcH + 4096, WrcL + 4096, KRC);

    // 1) edge_rep = edge_ctx @ w_post_emb + b
    conv_rows(edge_ctx, 512, Ehi, Elo, 512, N_OBJ);
    hm_gemm<EPI_BIAS,0><<<dim3(1024/128, N_OBJ/128), 128, HM_DSMEM>>>(
        Ehi, Elo, 512, WpeH, WpeL, 512, b_post_emb, nullptr, 0,
        edge_rep, 1024, nullptr, nullptr, 0, 1024, 512, HM_NOEXTRA);

    // 2) gather + split -> P hi/lo
    gather_hl<<<N_REL, 256>>>(edge_rep, rel_pairs, Phi, Plo);

    // 3) x_local = relu(union * (P @ Wpc + b)) -> Xc cols [200,4296);
    //    fused: union hi/lo split -> U (input of attn1)
    hm_gemm<EPI_MULRELU,1><<<dim3(POOL/128, N_REL/128), 128, HM_DSMEM>>>(
        Phi, Plo, 1024, WpcH, WpcL, 1024, b_post_cat, union_feat, POOL,
        nullptr, 0, Xchi + 200, Xclo + 200, KCATP, POOL, 1024,
        nullptr, nullptr, nullptr, nullptr, nullptr, 0, (1 << 30), Uhi, Ulo);

    // 4) LRGA-1 on union_features
    hm_gemm<EPI_RELU,0><<<dim3(512/128, N_REL/128), 128, HM_DSMEM>>>(
        Uhi, Ulo, POOL, Wa1H, Wa1L, POOL, b_attn1, nullptr, 0,
        tmp, 400, nullptr, nullptr, 0, 400, POOL, HM_NOEXTRA);
    lrga_part<<<64, 320>>>(tmp, 400, cs_part, vz_part, N_REL);
    lrga_reduce2<<<41, 256>>>(vz_part, vtz, cs_part, usvs, dscale);
    gemm_scalerelu_hl<<<dim3(1, N_REL/128), 256>>>(
        tmp, 400, vtz, 100, dscale, Xchi, Xclo, KCATP, N_REL, 100, 100);

    // 5) x = GN(relu(Xc @ Wd1 + b))
    hm_gemm<EPI_RELU,0><<<dim3(POOL/128, N_REL/128), 128, HM_DSMEM>>>(
        Xchi, Xclo, KCATP, Wd1H, Wd1L, KCATP, b_dr1, nullptr, 0,
        ybuf, POOL, nullptr, nullptr, 0, POOL, KCATP, HM_NOEXTRA);
    groupnorm_hl<<<N_REL, 256>>>(ybuf, gn_gamma, gn_beta, Uhi, Ulo, Xchi, Xclo);

    // 6) LRGA-2 on x
    hm_gemm<EPI_RELU,0><<<dim3(512/128, N_REL/128), 128, HM_DSMEM>>>(
        Uhi, Ulo, POOL, Wa2H, Wa2L, POOL, b_attn2, nullptr, 0,
        tmp, 400, nullptr, nullptr, 0, 400, POOL, HM_NOEXTRA);
    lrga_part<<<64, 320>>>(tmp, 400, cs_part, vz_part, N_REL);
    lrga_reduce2<<<41, 256>>>(vz_part, vtz, cs_part, usvs, dscale);
    gemm_scalerelu_hl<<<dim3(1, N_REL/128), 256>>>(
        tmp, 400, vtz, 100, dscale, Xchi, Xclo, KCATP, N_REL, 100, 100);

    // 7) visual = Xc @ Wd2 + b -> U hi/lo
    hm_gemm<EPI_BIAS,1><<<dim3(POOL/128, N_REL/128), 128, HM_DSMEM>>>(
        Xchi, Xclo, KCATP, Wd2H, Wd2L, KCATP, b_dr2, nullptr, 0,
        nullptr, 0, Uhi, Ulo, POOL, POOL, KCATP, HM_NOEXTRA);

    // 8) merged output: rel_dists = [visual | P] @ WrcT + (b_rel+b_ctx) + freq
    hm_gemm<EPI_BIASFREQ,0><<<dim3(1, N_REL/128), 128, HM_DSMEM>>>(
        Uhi, Ulo, POOL, WrcH, WrcL, KRC, bias_rc, nullptr, 0,
        out, NUM_REL, nullptr, nullptr, 0, NUM_REL, KRC,
        rel_pairs, obj_preds, freq_table,
        Phi, Plo, 1024, 4096, nullptr, nullptr);
}